// round 8
// baseline (speedup 1.0000x reference)
#include <cuda_runtime.h>
#include <cuda_bf16.h>
#include <math.h>
#include <stdint.h>

// Problem constants
#define B_  8
#define C_  256
#define H_  64
#define W_  64
#define HW_ 4096
#define NPIX 32768

// Scratch
__device__ float    g_qk[(size_t)NPIX * 64];     // fp32 q(32)|k(32), pixel-major
__device__ uint32_t g_vb[(size_t)NPIX * 128];    // bf16x2 v (256ch), pixel-major
__device__ uint4    g_wb4[320 * 32];             // bf16 W, [n][256ch], n-order q|k|v

#define SWZ(o) ((o) ^ (((o) >> 3) & 0x70))

__device__ __forceinline__ uint32_t pack_bf16(float lo, float hi) {
    uint32_t l = (uint32_t)__bfloat16_as_ushort(__float2bfloat16_rn(lo));
    uint32_t h = (uint32_t)__bfloat16_as_ushort(__float2bfloat16_rn(hi));
    return (h << 16) | l;
}

__device__ __forceinline__ void cp16(uint32_t dst, const void* src) {
    asm volatile("cp.async.cg.shared.global [%0], [%1], 16;" :: "r"(dst), "l"(src) : "memory");
}
// 8-byte cp.async with src-size: copies zn bytes, zero-fills the rest of 8.
// dst requires only 8-byte alignment (our 264B cell stride is 8-aligned).
__device__ __forceinline__ void cp8z(uint32_t dst, const void* src, int zn) {
    asm volatile("cp.async.ca.shared.global [%0], [%1], 8, %2;"
                 :: "r"(dst), "l"(src), "r"(zn) : "memory");
}

// ---------------------------------------------------------------------------
// Kernel 0: W -> bf16 (tiny; L2-resident afterwards). grid 40 x 256.
// ---------------------------------------------------------------------------
__global__ __launch_bounds__(256)
void prep_w(const float* __restrict__ Wq, const float* __restrict__ Wk,
            const float* __restrict__ Wv)
{
    int idx = blockIdx.x * 256 + threadIdx.x;          // 0..10239
    int n = idx >> 5, cg = idx & 31;
    const float* row = (n < 32) ? Wq + n * C_
                     : (n < 64) ? Wk + (n - 32) * C_
                                : Wv + (n - 64) * C_;
    const float* p = row + cg * 8;
    uint4 o;
    o.x = pack_bf16(p[0], p[1]); o.y = pack_bf16(p[2], p[3]);
    o.z = pack_bf16(p[4], p[5]); o.w = pack_bf16(p[6], p[7]);
    g_wb4[idx] = o;
}

// ---------------------------------------------------------------------------
// Kernel 1: fused x-convert + QKV GEMM (bf16 mma.sync). Unchanged (known-good).
// ---------------------------------------------------------------------------
#define XST_ROW 528
#define XST_SZ  (64 * XST_ROW)
#define OFF_B   65536
#define OFF_X   131072
#define GEMM_SMEM (OFF_X + 2 * XST_SZ + 1024)

__global__ __launch_bounds__(256)
void qkv_mma_gemm(const float* __restrict__ x,
                  const float* __restrict__ bq, const float* __restrict__ bk,
                  const float* __restrict__ bv)
{
    extern __shared__ unsigned char dsm[];
    __shared__ float sbias[320];

    const int tid  = threadIdx.x;
    const int lane = tid & 31;
    const int wid  = tid >> 5;
    const int wm   = wid >> 1;
    const int wn   = wid & 1;
    const int pix0 = blockIdx.x * 128;
    const int b    = pix0 >> 12;
    const int hw0  = pix0 & 4095;

    unsigned char* base = (unsigned char*)(((uintptr_t)dsm + 1023) & ~(uintptr_t)1023);
    const uint32_t As_u = (uint32_t)__cvta_generic_to_shared(base);
    const uint32_t Bs_u = As_u + OFF_B;
    const uint32_t Xs_u = As_u + OFF_X;

    for (int i = tid; i < 320; i += 256)
        sbias[i] = (i < 32) ? bq[i] : (i < 64) ? bk[i - 32] : bv[i - 64];

    const float* xb = x + ((size_t)b << 20) + hw0;

    #define ISSUE_X(kc, buf) do {                                             \
        uint32_t dst0 = Xs_u + (buf) * XST_SZ;                                \
        _Pragma("unroll")                                                     \
        for (int it = 0; it < 8; ++it) {                                      \
            int u = it * 256 + tid;                                           \
            int c = u >> 5, s = u & 31;                                       \
            cp16(dst0 + c * XST_ROW + s * 16,                                 \
                 xb + (size_t)((kc) * 64 + c) * HW_ + s * 4);                 \
        }                                                                     \
        asm volatile("cp.async.commit_group;" ::: "memory");                  \
    } while (0)

    #define ISSUE_B(nc, buf) do {                                             \
        const uint4* srcB = g_wb4 + (size_t)(nc) * 64 * 32;                   \
        uint32_t bb = Bs_u + (buf) * 32768;                                   \
        _Pragma("unroll")                                                     \
        for (int it = 0; it < 8; ++it) {                                      \
            int u = it * 256 + tid;                                           \
            int n = u >> 5, g = u & 31;                                       \
            cp16(bb + (g >> 3) * 8192 + SWZ(n * 128 + (g & 7) * 16), srcB + u);\
        }                                                                     \
        asm volatile("cp.async.commit_group;" ::: "memory");                  \
    } while (0)

    #define CONVERT(kc, buf) do {                                             \
        const float* xs = (const float*)(base + OFF_X + (buf) * XST_SZ);      \
        unsigned char* dA = base + (kc) * 16384;                              \
        const int p = tid & 127;                                              \
        const int hf = tid >> 7;                                              \
        _Pragma("unroll")                                                     \
        for (int t = 0; t < 16; ++t) {                                        \
            int c2 = hf * 16 + t;                                             \
            uint32_t w = pack_bf16(xs[(2 * c2) * 132 + p],                    \
                                   xs[(2 * c2 + 1) * 132 + p]);               \
            *(uint32_t*)(dA + SWZ(p * 128 + c2 * 4)) = w;                     \
        }                                                                     \
    } while (0)

    ISSUE_X(0, 0);
    ISSUE_X(1, 1);
    ISSUE_B(0, 0);

    asm volatile("cp.async.wait_group 2;" ::: "memory");
    __syncthreads();
    CONVERT(0, 0);
    __syncthreads();
    ISSUE_X(2, 0);

    asm volatile("cp.async.wait_group 2;" ::: "memory");
    __syncthreads();
    CONVERT(1, 1);
    __syncthreads();
    ISSUE_X(3, 1);

    asm volatile("cp.async.wait_group 1;" ::: "memory");
    __syncthreads();
    CONVERT(2, 0);
    __syncthreads();

    asm volatile("cp.async.wait_group 0;" ::: "memory");
    __syncthreads();
    CONVERT(3, 1);
    __syncthreads();

    const int a_row  = (lane & 15);
    const int a_koff = (lane >> 4) << 4;
    const int b_r    = (lane & 7);
    const int b_grp  = lane >> 3;
    const int b_nrow = ((b_grp >> 1) << 3) + b_r;
    const int b_koff = (b_grp & 1) << 4;

    for (int nc = 0; nc < 5; ++nc) {
        if (nc < 4) ISSUE_B(nc + 1, (nc + 1) & 1);
        const uint32_t Bcur = Bs_u + (nc & 1) * 32768;

        float acc[2][4][4];
        #pragma unroll
        for (int mi = 0; mi < 2; mi++)
            #pragma unroll
            for (int nj = 0; nj < 4; nj++)
                #pragma unroll
                for (int q = 0; q < 4; q++) acc[mi][nj][q] = 0.f;

        #pragma unroll
        for (int kt = 0; kt < 16; ++kt) {
            const int chunk = kt >> 2;
            const int kb    = (kt & 3) * 32;

            uint32_t af[2][4];
            #pragma unroll
            for (int mi = 0; mi < 2; mi++) {
                int row = wm * 32 + mi * 16 + a_row;
                uint32_t ad = As_u + chunk * 16384 + SWZ(row * 128 + kb + a_koff);
                asm volatile("ldmatrix.sync.aligned.m8n8.x4.shared.b16 {%0,%1,%2,%3}, [%4];"
                             : "=r"(af[mi][0]), "=r"(af[mi][1]), "=r"(af[mi][2]), "=r"(af[mi][3])
                             : "r"(ad));
            }
            uint32_t bf[2][4];
            #pragma unroll
            for (int njp = 0; njp < 2; njp++) {
                int n = wn * 32 + njp * 16 + b_nrow;
                uint32_t bd = Bcur + chunk * 8192 + SWZ(n * 128 + kb + b_koff);
                asm volatile("ldmatrix.sync.aligned.m8n8.x4.shared.b16 {%0,%1,%2,%3}, [%4];"
                             : "=r"(bf[njp][0]), "=r"(bf[njp][1]), "=r"(bf[njp][2]), "=r"(bf[njp][3])
                             : "r"(bd));
            }
            #pragma unroll
            for (int mi = 0; mi < 2; mi++)
                #pragma unroll
                for (int nj = 0; nj < 4; nj++) {
                    uint32_t b0 = bf[nj >> 1][(nj & 1) * 2 + 0];
                    uint32_t b1 = bf[nj >> 1][(nj & 1) * 2 + 1];
                    asm volatile(
                        "mma.sync.aligned.m16n8k16.row.col.f32.bf16.bf16.f32 "
                        "{%0,%1,%2,%3}, {%4,%5,%6,%7}, {%8,%9}, {%0,%1,%2,%3};"
                        : "+f"(acc[mi][nj][0]), "+f"(acc[mi][nj][1]),
                          "+f"(acc[mi][nj][2]), "+f"(acc[mi][nj][3])
                        : "r"(af[mi][0]), "r"(af[mi][1]), "r"(af[mi][2]), "r"(af[mi][3]),
                          "r"(b0), "r"(b1));
                }
        }

        {
            const int colq = (lane & 3) * 2;
            const int rowq = lane >> 2;
            #pragma unroll
            for (int mi = 0; mi < 2; mi++) {
                int r0 = pix0 + wm * 32 + mi * 16 + rowq;
                #pragma unroll
                for (int nj = 0; nj < 4; nj++) {
                    int col = nc * 64 + wn * 32 + nj * 8 + colq;
                    float bs0 = sbias[col], bs1 = sbias[col + 1];
                    float v00 = acc[mi][nj][0] + bs0, v01 = acc[mi][nj][1] + bs1;
                    float v10 = acc[mi][nj][2] + bs0, v11 = acc[mi][nj][3] + bs1;
                    if (nc == 0) {
                        *(float2*)(g_qk + (size_t)r0 * 64 + col)       = make_float2(v00, v01);
                        *(float2*)(g_qk + (size_t)(r0 + 8) * 64 + col) = make_float2(v10, v11);
                    } else {
                        int vcol2 = (col - 64) >> 1;
                        g_vb[(size_t)r0 * 128 + vcol2]       = pack_bf16(v00, v01);
                        g_vb[(size_t)(r0 + 8) * 128 + vcol2] = pack_bf16(v10, v11);
                    }
                }
            }
        }

        if (nc < 4) {
            asm volatile("cp.async.wait_group 0;" ::: "memory");
            __syncthreads();
        }
    }
}

// ---------------------------------------------------------------------------
// Kernel 2: local 3x3 window attention + residual.
//   q/k fp32, v bf16. v chunks prefetched via 8-byte cp.async (zero-fill for
//   OOB, dst 8-aligned at 264B cell stride) into dedicated double buffers:
//   chunk0 issued at kernel start (lands under q/k load + energies + softmax),
//   chunk1 issued after softmax (lands under chunk0 compute + stores).
// ---------------------------------------------------------------------------
#define PTILE 32
#define KCOLS 34
#define VROWU 66                      // u32 per (r,col) cell: 64 data + 2 pad
#define VBUF_BYTES (3 * KCOLS * VROWU * 4)       // 26928
#define SQ_F 0                        // f32 idx: sq [32][33]
#define SK_F (PTILE * 33)             // sk [3*34][33]
#define SE_F (SK_F + 3 * KCOLS * 33)  // se [288]
#define V0_BYTE 18944                 // 16B-aligned, past (SE_F+288)*4=18840
#define V1_BYTE (V0_BYTE + VBUF_BYTES)
#define ATTN_SMEM (V1_BYTE + VBUF_BYTES)         // 72800

__global__ __launch_bounds__(256)
void attn_kernel(const float* __restrict__ x,
                 const float* __restrict__ gamma,
                 float* __restrict__ out)
{
    extern __shared__ unsigned char asm_raw[];
    float*    sf  = (float*)asm_raw;
    const uint32_t smem_u32 = (uint32_t)__cvta_generic_to_shared(asm_raw);

    const int tid   = threadIdx.x;
    const int b     = blockIdx.y;
    const int h     = blockIdx.x >> 1;
    const int wbase = (blockIdx.x & 1) * PTILE;
    const int pixrow = b * HW_ + h * W_;
    const float g0 = gamma[0];

    // ---- v prefetch: 102 cells x 32 x 8B units (8B cp.async, zfill OOB) ----
    #define ISSUE_V(chunk, vbyte) do {                                        \
        uint32_t dst0 = smem_u32 + (vbyte);                                   \
        for (int u = tid; u < 3 * KCOLS * 32; u += 256) {                     \
            int q8   = u & 31;                                                \
            int cell = u >> 5;                                                \
            int col  = cell % KCOLS;                                          \
            int r    = cell / KCOLS;                                          \
            int hh   = h + r - 1;                                             \
            int ww   = wbase + col - 1;                                       \
            int ok   = (hh >= 0) & (hh < H_) & (ww >= 0) & (ww < W_);         \
            const uint32_t* src = g_vb                                        \
                + (size_t)(b * HW_ + (ok ? hh * W_ + ww : 0)) * 128           \
                + (chunk) * 64 + q8 * 2;                                      \
            cp8z(dst0 + cell * (VROWU * 4) + q8 * 8, src, ok ? 8 : 0);        \
        }                                                                     \
        asm volatile("cp.async.commit_group;" ::: "memory");                  \
    } while (0)

    ISSUE_V(0, V0_BYTE);

    // ---- q tile + k halo loads (fp32) ----
    for (int idx = tid; idx < PTILE * 32; idx += 256) {
        int p = idx >> 5, c = idx & 31;
        sf[SQ_F + p * 33 + c] = g_qk[(size_t)(pixrow + wbase + p) * 64 + c];
    }
    for (int idx = tid; idx < 3 * KCOLS * 32; idx += 256) {
        int c    = idx & 31;
        int rest = idx >> 5;
        int col  = rest % KCOLS;
        int r    = rest / KCOLS;
        int hh   = h + r - 1;
        int ww   = wbase + col - 1;
        float v = 0.f;
        if (hh >= 0 && hh < H_ && ww >= 0 && ww < W_)
            v = g_qk[(size_t)(b * HW_ + hh * W_ + ww) * 64 + 32 + c];
        sf[SK_F + (r * KCOLS + col) * 33 + c] = v;
    }
    __syncthreads();

    // ---- Energies (288 tasks) ----
    for (int task = tid; task < PTILE * 9; task += 256) {
        int p = task / 9, j = task % 9;
        int r = j / 3, dx = j % 3;
        const float* qp = sf + SQ_F + p * 33;
        const float* kp = sf + SK_F + (r * KCOLS + p + dx) * 33;
        float e = 0.f;
        #pragma unroll
        for (int c = 0; c < 32; c++) e = fmaf(qp[c], kp[c], e);
        sf[SE_F + p * 9 + j] = e;
    }
    __syncthreads();

    // ---- Softmax over 9 (OOB zeros stay in denominator) ----
    if (tid < PTILE) {
        float e[9], m = -1e30f;
        #pragma unroll
        for (int j = 0; j < 9; j++) { e[j] = sf[SE_F + tid * 9 + j]; m = fmaxf(m, e[j]); }
        float s = 0.f;
        #pragma unroll
        for (int j = 0; j < 9; j++) { e[j] = expf(e[j] - m); s += e[j]; }
        float inv = 1.f / s;
        #pragma unroll
        for (int j = 0; j < 9; j++) sf[SE_F + tid * 9 + j] = e[j] * inv;
    }

    // ---- Prefetch v chunk 1, then wait for chunk 0 ----
    ISSUE_V(1, V1_BYTE);
    asm volatile("cp.async.wait_group 1;" ::: "memory");
    __syncthreads();   // chunk0 visible block-wide; softmax writes visible

    const int p  = tid & 31;
    const int cg = tid >> 5;
    float a[9];
    #pragma unroll
    for (int j = 0; j < 9; j++) a[j] = sf[SE_F + p * 9 + j];

    int basej[9];
    #pragma unroll
    for (int j = 0; j < 9; j++)
        basej[j] = ((j / 3) * KCOLS + p + (j % 3)) * VROWU + cg * 8;

    #pragma unroll
    for (int chunk = 0; chunk < 2; ++chunk) {
        const uint32_t* vbuf = (const uint32_t*)(asm_raw + (chunk ? V1_BYTE : V0_BYTE));

        float acc[16];
        #pragma unroll
        for (int i = 0; i < 16; i++) acc[i] = 0.f;
        #pragma unroll
        for (int j = 0; j < 9; j++) {
            const uint32_t* svp = vbuf + basej[j];
            float aj = a[j];
            #pragma unroll
            for (int u = 0; u < 8; u++) {
                uint32_t w = svp[u];
                float2 f = __bfloat1622float2(*(const __nv_bfloat162*)&w);
                acc[2 * u + 0] = fmaf(aj, f.x, acc[2 * u + 0]);
                acc[2 * u + 1] = fmaf(aj, f.y, acc[2 * u + 1]);
            }
        }

        // out = gamma*o + x  (coalesced along w)
        #pragma unroll
        for (int i = 0; i < 16; i++) {
            int cglob = chunk * 128 + cg * 16 + i;
            size_t xi = ((size_t)(b * C_ + cglob)) * HW_ + h * W_ + wbase + p;
            out[xi] = fmaf(g0, acc[i], x[xi]);
        }

        if (chunk == 0) {
            asm volatile("cp.async.wait_group 0;" ::: "memory");
            __syncthreads();
        }
    }
}

// ---------------------------------------------------------------------------
extern "C" void kernel_launch(void* const* d_in, const int* in_sizes, int n_in,
                              void* d_out, int out_size)
{
    const float* x     = (const float*)d_in[0];
    const float* Wq    = (const float*)d_in[1];
    const float* bq    = (const float*)d_in[2];
    const float* Wk    = (const float*)d_in[3];
    const float* bk    = (const float*)d_in[4];
    const float* Wv    = (const float*)d_in[5];
    const float* bv    = (const float*)d_in[6];
    const float* gamma = (const float*)d_in[7];
    float* out = (float*)d_out;

    cudaFuncSetAttribute(qkv_mma_gemm, cudaFuncAttributeMaxDynamicSharedMemorySize, GEMM_SMEM);
    cudaFuncSetAttribute(attn_kernel,  cudaFuncAttributeMaxDynamicSharedMemorySize, ATTN_SMEM);

    prep_w<<<40, 256>>>(Wq, Wk, Wv);
    qkv_mma_gemm<<<256, 256, GEMM_SMEM>>>(x, bq, bk, bv);

    dim3 agrid(H_ * 2, B_);
    attn_kernel<<<agrid, 256, ATTN_SMEM>>>(x, gamma, out);
}

// round 9
// speedup vs baseline: 1.0153x; 1.0153x over previous
#include <cuda_runtime.h>
#include <cuda_bf16.h>
#include <math.h>
#include <stdint.h>

// Problem constants
#define B_  8
#define C_  256
#define H_  64
#define W_  64
#define HW_ 4096
#define NPIX 32768

// Scratch
__device__ float    g_qk[(size_t)NPIX * 64];     // fp32 q(32)|k(32), pixel-major
__device__ uint32_t g_vb[(size_t)NPIX * 128];    // bf16x2 v (256ch), pixel-major
__device__ uint4    g_wb4[320 * 32];             // bf16 W, [n][256ch], n-order q|k|v

#define SWZ(o) ((o) ^ (((o) >> 3) & 0x70))

__device__ __forceinline__ uint32_t pack_bf16(float lo, float hi) {
    uint32_t l = (uint32_t)__bfloat16_as_ushort(__float2bfloat16_rn(lo));
    uint32_t h = (uint32_t)__bfloat16_as_ushort(__float2bfloat16_rn(hi));
    return (h << 16) | l;
}

__device__ __forceinline__ void cp16(uint32_t dst, const void* src) {
    asm volatile("cp.async.cg.shared.global [%0], [%1], 16;" :: "r"(dst), "l"(src) : "memory");
}

// ---------------------------------------------------------------------------
// Kernel 0: W -> bf16 (tiny; L2-resident afterwards). grid 40 x 256.
// ---------------------------------------------------------------------------
__global__ __launch_bounds__(256)
void prep_w(const float* __restrict__ Wq, const float* __restrict__ Wk,
            const float* __restrict__ Wv)
{
    int idx = blockIdx.x * 256 + threadIdx.x;          // 0..10239
    int n = idx >> 5, cg = idx & 31;
    const float* row = (n < 32) ? Wq + n * C_
                     : (n < 64) ? Wk + (n - 32) * C_
                                : Wv + (n - 64) * C_;
    const float* p = row + cg * 8;
    uint4 o;
    o.x = pack_bf16(p[0], p[1]); o.y = pack_bf16(p[2], p[3]);
    o.z = pack_bf16(p[4], p[5]); o.w = pack_bf16(p[6], p[7]);
    g_wb4[idx] = o;
}

// ---------------------------------------------------------------------------
// Kernel 1: fused x-convert + QKV GEMM (bf16 mma.sync).
//   CTA = 128-pixel M-tile x full N=320 (10 chunks of 32). K=256.
//   A: x converted in-kernel global->reg->smem, stored TRANSPOSED as
//      [half(p>=64)][c:256][64px] bf16 SW128 rows, fed to MMA via
//      ldmatrix.x4.trans (no fp32 staging, no extra sync stages).
//   B: double-buffered 16KB n-chunks (32 n x 256 c) via cp.async.
//   Smem 97KB -> 2 CTAs/SM -> single wave for 256 CTAs.
// ---------------------------------------------------------------------------
#define GEMM_SMEM (65536 + 2 * 16384 + 1024)   // 99328

__global__ __launch_bounds__(256)
void qkv_mma_gemm(const float* __restrict__ x,
                  const float* __restrict__ bq, const float* __restrict__ bk,
                  const float* __restrict__ bv)
{
    extern __shared__ unsigned char dsm[];
    __shared__ float sbias[320];

    const int tid  = threadIdx.x;
    const int lane = tid & 31;
    const int wid  = tid >> 5;
    const int wm   = wid >> 1;          // 0..3 (M: 32 px each)
    const int wn   = wid & 1;           // 0..1 (N: 16 each)
    const int pix0 = blockIdx.x * 128;
    const int b    = pix0 >> 12;
    const int hw0  = pix0 & 4095;

    unsigned char* base = (unsigned char*)(((uintptr_t)dsm + 1023) & ~(uintptr_t)1023);
    const uint32_t As_u = (uint32_t)__cvta_generic_to_shared(base);
    const uint32_t Bs_u = As_u + 65536;

    for (int i = tid; i < 320; i += 256)
        sbias[i] = (i < 32) ? bq[i] : (i < 64) ? bk[i - 32] : bv[i - 64];

    // B chunk: 32 n-rows x 32 uint4 (512B/row) -> [4 kchunks][32n][128B] swizzled
    #define ISSUE_B(nc, buf) do {                                             \
        const uint4* srcB = g_wb4 + (size_t)(nc) * 32 * 32;                   \
        uint32_t bb = Bs_u + (buf) * 16384;                                   \
        _Pragma("unroll")                                                     \
        for (int it = 0; it < 4; ++it) {                                      \
            int u = it * 256 + tid;                                           \
            int n = u >> 5, g = u & 31;                                       \
            cp16(bb + (g >> 3) * 4096 + SWZ(n * 128 + (g & 7) * 16), srcB + u);\
        }                                                                     \
        asm volatile("cp.async.commit_group;" ::: "memory");                  \
    } while (0)

    ISSUE_B(0, 0);
    ISSUE_B(1, 1);

    // ---- A convert: x[b][c][hw0+p] fp32 -> As[half][c][64px] bf16 swizzled.
    // Warp handles one c-row of 128 px per iter: LDG.128 coalesced, STS.64
    // conflict-free (half-warp covers one swizzled 128B segment).
    {
        const float4* xsrc = (const float4*)(x + ((size_t)b << 20) + hw0);
        #pragma unroll
        for (int it = 0; it < 32; ++it) {
            int u = it * 256 + tid;
            int c = u >> 5, q = u & 31;
            float4 v = xsrc[(size_t)c * 1024 + q];
            uint32_t w0, w1;
            asm("cvt.rn.bf16x2.f32 %0, %1, %2;" : "=r"(w0) : "f"(v.y), "f"(v.x));
            asm("cvt.rn.bf16x2.f32 %0, %1, %2;" : "=r"(w1) : "f"(v.w), "f"(v.z));
            int p0 = q * 4;
            uint32_t dst = As_u + ((p0 >> 6) << 15) + SWZ(c * 128 + (p0 & 63) * 2);
            asm volatile("st.shared.v2.b32 [%0], {%1,%2};" :: "r"(dst), "r"(w0), "r"(w1) : "memory");
        }
    }
    __syncthreads();

    // ldmatrix lane-address components
    // A (trans, from [c][px] storage): groups {(m0,k0),(m+8,k0),(m0,k+8),(m+8,k+8)}
    const int at_c = ((lane >> 4) << 3) + (lane & 7);   // c offset within k16
    const int at_m = ((lane >> 3) & 1) << 3;            // px offset 0/8
    // B (non-trans, rows of k): same as previous rounds
    const int b_r    = (lane & 7);
    const int b_grp  = lane >> 3;
    const int b_nrow = ((b_grp >> 1) << 3) + b_r;
    const int b_koff = (b_grp & 1) << 4;

    const int colq = (lane & 3) * 2;
    const int rowq = lane >> 2;

    for (int nc = 0; nc < 10; ++nc) {
        asm volatile("cp.async.wait_group 1;" ::: "memory");
        __syncthreads();
        const uint32_t Bcur = Bs_u + (nc & 1) * 16384;

        float acc[2][2][4];
        #pragma unroll
        for (int mi = 0; mi < 2; mi++)
            #pragma unroll
            for (int nj = 0; nj < 2; nj++)
                #pragma unroll
                for (int q = 0; q < 4; q++) acc[mi][nj][q] = 0.f;

        #pragma unroll
        for (int kt = 0; kt < 16; ++kt) {
            const int c0 = kt * 16;

            uint32_t af[2][4];
            #pragma unroll
            for (int mi = 0; mi < 2; mi++) {
                int p = wm * 32 + mi * 16 + at_m;
                int c = c0 + at_c;
                uint32_t ad = As_u + ((p >> 6) << 15) + SWZ(c * 128 + (p & 63) * 2);
                asm volatile("ldmatrix.sync.aligned.m8n8.x4.trans.shared.b16 {%0,%1,%2,%3}, [%4];"
                             : "=r"(af[mi][0]), "=r"(af[mi][1]), "=r"(af[mi][2]), "=r"(af[mi][3])
                             : "r"(ad));
            }
            uint32_t bf4[4];
            {
                int n = wn * 16 + b_nrow;
                uint32_t bd = Bcur + (kt >> 2) * 4096 + SWZ(n * 128 + (kt & 3) * 32 + b_koff);
                asm volatile("ldmatrix.sync.aligned.m8n8.x4.shared.b16 {%0,%1,%2,%3}, [%4];"
                             : "=r"(bf4[0]), "=r"(bf4[1]), "=r"(bf4[2]), "=r"(bf4[3])
                             : "r"(bd));
            }
            #pragma unroll
            for (int mi = 0; mi < 2; mi++)
                #pragma unroll
                for (int nj = 0; nj < 2; nj++) {
                    asm volatile(
                        "mma.sync.aligned.m16n8k16.row.col.f32.bf16.bf16.f32 "
                        "{%0,%1,%2,%3}, {%4,%5,%6,%7}, {%8,%9}, {%0,%1,%2,%3};"
                        : "+f"(acc[mi][nj][0]), "+f"(acc[mi][nj][1]),
                          "+f"(acc[mi][nj][2]), "+f"(acc[mi][nj][3])
                        : "r"(af[mi][0]), "r"(af[mi][1]), "r"(af[mi][2]), "r"(af[mi][3]),
                          "r"(bf4[nj * 2 + 0]), "r"(bf4[nj * 2 + 1]));
                }
        }

        __syncthreads();                       // all warps done with buf nc&1
        if (nc + 2 < 10) ISSUE_B(nc + 2, nc & 1);

        // Epilogue: nc 0-1 -> fp32 q|k (cols 0..63); nc 2-9 -> bf16x2 v
        #pragma unroll
        for (int mi = 0; mi < 2; mi++) {
            int r0 = pix0 + wm * 32 + mi * 16 + rowq;
            #pragma unroll
            for (int nj = 0; nj < 2; nj++) {
                int col = nc * 32 + wn * 16 + nj * 8 + colq;
                float bs0 = sbias[col], bs1 = sbias[col + 1];
                float v00 = acc[mi][nj][0] + bs0, v01 = acc[mi][nj][1] + bs1;
                float v10 = acc[mi][nj][2] + bs0, v11 = acc[mi][nj][3] + bs1;
                if (nc < 2) {
                    *(float2*)(g_qk + (size_t)r0 * 64 + col)       = make_float2(v00, v01);
                    *(float2*)(g_qk + (size_t)(r0 + 8) * 64 + col) = make_float2(v10, v11);
                } else {
                    int vcol2 = (col - 64) >> 1;
                    g_vb[(size_t)r0 * 128 + vcol2]       = pack_bf16(v00, v01);
                    g_vb[(size_t)(r0 + 8) * 128 + vcol2] = pack_bf16(v10, v11);
                }
            }
        }
    }
}

// ---------------------------------------------------------------------------
// Kernel 2: local 3x3 window attention + residual (R5 version, known-good:
//   static ~28KB smem -> 8 CTAs/SM, cross-CTA parallelism hides latency).
// ---------------------------------------------------------------------------
#define PTILE 32
#define KCOLS 34
#define VROW  66     // uint32 per (r,col) v row: 64 data + 2 pad (2-way bank max)

__global__ __launch_bounds__(256)
void attn_kernel(const float* __restrict__ x,
                 const float* __restrict__ gamma,
                 float* __restrict__ out)
{
    __shared__ uint32_t smem_u[3 * KCOLS * VROW];     // 6732 u32 = 26928 B
    __shared__ float se[PTILE * 9];

    float* sq = (float*)smem_u;                        // [32][33]
    float* sk = (float*)smem_u + PTILE * 33;           // [3][34][33]

    const int tid   = threadIdx.x;
    const int b     = blockIdx.y;
    const int h     = blockIdx.x >> 1;
    const int wbase = (blockIdx.x & 1) * PTILE;
    const int pixrow = b * HW_ + h * W_;
    const float g0 = gamma[0];

    // Phase 1: load q tile + k halo (fp32 from g_qk)
    for (int idx = tid; idx < PTILE * 32; idx += 256) {
        int p = idx >> 5, c = idx & 31;
        sq[p * 33 + c] = g_qk[(size_t)(pixrow + wbase + p) * 64 + c];
    }
    for (int idx = tid; idx < 3 * KCOLS * 32; idx += 256) {
        int c    = idx & 31;
        int rest = idx >> 5;
        int col  = rest % KCOLS;
        int r    = rest / KCOLS;
        int hh   = h + r - 1;
        int ww   = wbase + col - 1;
        float v = 0.f;
        if (hh >= 0 && hh < H_ && ww >= 0 && ww < W_)
            v = g_qk[(size_t)(b * HW_ + hh * W_ + ww) * 64 + 32 + c];
        sk[(r * KCOLS + col) * 33 + c] = v;
    }
    __syncthreads();

    // Energies (288 tasks)
    for (int task = tid; task < PTILE * 9; task += 256) {
        int p = task / 9, j = task % 9;
        int r = j / 3, dx = j % 3;
        const float* qp = sq + p * 33;
        const float* kp = sk + (r * KCOLS + p + dx) * 33;
        float e = 0.f;
        #pragma unroll
        for (int c = 0; c < 32; c++) e = fmaf(qp[c], kp[c], e);
        se[p * 9 + j] = e;
    }
    __syncthreads();

    // Softmax over 9 (OOB zeros stay in denominator, matching reference)
    if (tid < PTILE) {
        float e[9], m = -1e30f;
        #pragma unroll
        for (int j = 0; j < 9; j++) { e[j] = se[tid * 9 + j]; m = fmaxf(m, e[j]); }
        float s = 0.f;
        #pragma unroll
        for (int j = 0; j < 9; j++) { e[j] = expf(e[j] - m); s += e[j]; }
        float inv = 1.f / s;
        #pragma unroll
        for (int j = 0; j < 9; j++) se[tid * 9 + j] = e[j] * inv;
    }
    __syncthreads();

    // Phase 3: v accumulation, 2 chunks of 128 bf16 channels
    const int p  = tid & 31;
    const int cg = tid >> 5;          // 0..7 -> 16 channels each
    float a[9];
    #pragma unroll
    for (int j = 0; j < 9; j++) a[j] = se[p * 9 + j];

    int basej[9];
    #pragma unroll
    for (int j = 0; j < 9; j++)
        basej[j] = ((j / 3) * KCOLS + p + (j % 3)) * VROW + cg * 8;

    for (int chunk = 0; chunk < 2; ++chunk) {
        __syncthreads();
        // load v halo chunk: 3*34 cols x 32 uint2 (=64 u32) each
        uint2* sv2 = (uint2*)smem_u;
        for (int idx = tid; idx < 3 * KCOLS * 32; idx += 256) {
            int c2   = idx & 31;
            int rest = idx >> 5;
            int col  = rest % KCOLS;
            int r    = rest / KCOLS;
            int hh   = h + r - 1;
            int ww   = wbase + col - 1;
            uint2 v = make_uint2(0u, 0u);
            if (hh >= 0 && hh < H_ && ww >= 0 && ww < W_)
                v = *(const uint2*)(g_vb + (size_t)(b * HW_ + hh * W_ + ww) * 128
                                    + chunk * 64 + c2 * 2);
            sv2[(r * KCOLS + col) * 33 + c2] = v;
        }
        __syncthreads();

        float acc[16];
        #pragma unroll
        for (int i = 0; i < 16; i++) acc[i] = 0.f;
        #pragma unroll
        for (int j = 0; j < 9; j++) {
            const uint32_t* svp = smem_u + basej[j];
            float aj = a[j];
            #pragma unroll
            for (int u = 0; u < 8; u++) {
                uint32_t w = svp[u];
                float2 f = __bfloat1622float2(*(const __nv_bfloat162*)&w);
                acc[2 * u + 0] = fmaf(aj, f.x, acc[2 * u + 0]);
                acc[2 * u + 1] = fmaf(aj, f.y, acc[2 * u + 1]);
            }
        }

        // out = gamma*o + x  (coalesced along w)
        #pragma unroll
        for (int i = 0; i < 16; i++) {
            int cglob = chunk * 128 + cg * 16 + i;
            size_t xi = ((size_t)(b * C_ + cglob)) * HW_ + h * W_ + wbase + p;
            out[xi] = fmaf(g0, acc[i], x[xi]);
        }
    }
}

// ---------------------------------------------------------------------------
extern "C" void kernel_launch(void* const* d_in, const int* in_sizes, int n_in,
                              void* d_out, int out_size)
{
    const float* x     = (const float*)d_in[0];
    const float* Wq    = (const float*)d_in[1];
    const float* bq    = (const float*)d_in[2];
    const float* Wk    = (const float*)d_in[3];
    const float* bk    = (const float*)d_in[4];
    const float* Wv    = (const float*)d_in[5];
    const float* bv    = (const float*)d_in[6];
    const float* gamma = (const float*)d_in[7];
    float* out = (float*)d_out;

    cudaFuncSetAttribute(qkv_mma_gemm, cudaFuncAttributeMaxDynamicSharedMemorySize, GEMM_SMEM);

    prep_w<<<40, 256>>>(Wq, Wk, Wv);
    qkv_mma_gemm<<<256, 256, GEMM_SMEM>>>(x, bq, bk, bv);

    dim3 agrid(H_ * 2, B_);
    attn_kernel<<<agrid, 256>>>(x, gamma, out);
}

// round 10
// speedup vs baseline: 1.0907x; 1.0743x over previous
#include <cuda_runtime.h>
#include <cuda_bf16.h>
#include <math.h>
#include <stdint.h>

// Problem constants
#define B_  8
#define C_  256
#define H_  64
#define W_  64
#define HW_ 4096
#define NPIX 32768

// Scratch
__device__ float    g_qk[(size_t)NPIX * 64];     // fp32 q(32)|k(32), pixel-major
__device__ uint32_t g_vb[(size_t)NPIX * 128];    // bf16x2 v (256ch), pixel-major
__device__ uint4    g_wb4[320 * 32];             // bf16 W, [n][256ch], n-order q|k|v

#define SWZ(o) ((o) ^ (((o) >> 3) & 0x70))

__device__ __forceinline__ uint32_t pack_bf16(float lo, float hi) {
    uint32_t l = (uint32_t)__bfloat16_as_ushort(__float2bfloat16_rn(lo));
    uint32_t h = (uint32_t)__bfloat16_as_ushort(__float2bfloat16_rn(hi));
    return (h << 16) | l;
}

__device__ __forceinline__ void cp16(uint32_t dst, const void* src) {
    asm volatile("cp.async.cg.shared.global [%0], [%1], 16;" :: "r"(dst), "l"(src) : "memory");
}

// ---------------------------------------------------------------------------
// Kernel 0: W -> bf16 (tiny; L2-resident afterwards). grid 40 x 256.
// ---------------------------------------------------------------------------
__global__ __launch_bounds__(256)
void prep_w(const float* __restrict__ Wq, const float* __restrict__ Wk,
            const float* __restrict__ Wv)
{
    int idx = blockIdx.x * 256 + threadIdx.x;          // 0..10239
    int n = idx >> 5, cg = idx & 31;
    const float* row = (n < 32) ? Wq + n * C_
                     : (n < 64) ? Wk + (n - 32) * C_
                                : Wv + (n - 64) * C_;
    const float* p = row + cg * 8;
    uint4 o;
    o.x = pack_bf16(p[0], p[1]); o.y = pack_bf16(p[2], p[3]);
    o.z = pack_bf16(p[4], p[5]); o.w = pack_bf16(p[6], p[7]);
    g_wb4[idx] = o;
}

// ---------------------------------------------------------------------------
// Kernel 1: fused x-convert + QKV GEMM (bf16 mma.sync). R5 version (known-good).
// ---------------------------------------------------------------------------
#define XST_ROW 528
#define XST_SZ  (64 * XST_ROW)
#define OFF_B   65536
#define OFF_X   131072
#define GEMM_SMEM (OFF_X + 2 * XST_SZ + 1024)

__global__ __launch_bounds__(256)
void qkv_mma_gemm(const float* __restrict__ x,
                  const float* __restrict__ bq, const float* __restrict__ bk,
                  const float* __restrict__ bv)
{
    extern __shared__ unsigned char dsm[];
    __shared__ float sbias[320];

    const int tid  = threadIdx.x;
    const int lane = tid & 31;
    const int wid  = tid >> 5;
    const int wm   = wid >> 1;
    const int wn   = wid & 1;
    const int pix0 = blockIdx.x * 128;
    const int b    = pix0 >> 12;
    const int hw0  = pix0 & 4095;

    unsigned char* base = (unsigned char*)(((uintptr_t)dsm + 1023) & ~(uintptr_t)1023);
    const uint32_t As_u = (uint32_t)__cvta_generic_to_shared(base);
    const uint32_t Bs_u = As_u + OFF_B;
    const uint32_t Xs_u = As_u + OFF_X;

    for (int i = tid; i < 320; i += 256)
        sbias[i] = (i < 32) ? bq[i] : (i < 64) ? bk[i - 32] : bv[i - 64];

    const float* xb = x + ((size_t)b << 20) + hw0;

    #define ISSUE_X(kc, buf) do {                                             \
        uint32_t dst0 = Xs_u + (buf) * XST_SZ;                                \
        _Pragma("unroll")                                                     \
        for (int it = 0; it < 8; ++it) {                                      \
            int u = it * 256 + tid;                                           \
            int c = u >> 5, s = u & 31;                                       \
            cp16(dst0 + c * XST_ROW + s * 16,                                 \
                 xb + (size_t)((kc) * 64 + c) * HW_ + s * 4);                 \
        }                                                                     \
        asm volatile("cp.async.commit_group;" ::: "memory");                  \
    } while (0)

    #define ISSUE_B(nc, buf) do {                                             \
        const uint4* srcB = g_wb4 + (size_t)(nc) * 64 * 32;                   \
        uint32_t bb = Bs_u + (buf) * 32768;                                   \
        _Pragma("unroll")                                                     \
        for (int it = 0; it < 8; ++it) {                                      \
            int u = it * 256 + tid;                                           \
            int n = u >> 5, g = u & 31;                                       \
            cp16(bb + (g >> 3) * 8192 + SWZ(n * 128 + (g & 7) * 16), srcB + u);\
        }                                                                     \
        asm volatile("cp.async.commit_group;" ::: "memory");                  \
    } while (0)

    #define CONVERT(kc, buf) do {                                             \
        const float* xs = (const float*)(base + OFF_X + (buf) * XST_SZ);      \
        unsigned char* dA = base + (kc) * 16384;                              \
        const int p = tid & 127;                                              \
        const int hf = tid >> 7;                                              \
        _Pragma("unroll")                                                     \
        for (int t = 0; t < 16; ++t) {                                        \
            int c2 = hf * 16 + t;                                             \
            uint32_t w = pack_bf16(xs[(2 * c2) * 132 + p],                    \
                                   xs[(2 * c2 + 1) * 132 + p]);               \
            *(uint32_t*)(dA + SWZ(p * 128 + c2 * 4)) = w;                     \
        }                                                                     \
    } while (0)

    ISSUE_X(0, 0);
    ISSUE_X(1, 1);
    ISSUE_B(0, 0);

    asm volatile("cp.async.wait_group 2;" ::: "memory");
    __syncthreads();
    CONVERT(0, 0);
    __syncthreads();
    ISSUE_X(2, 0);

    asm volatile("cp.async.wait_group 2;" ::: "memory");
    __syncthreads();
    CONVERT(1, 1);
    __syncthreads();
    ISSUE_X(3, 1);

    asm volatile("cp.async.wait_group 1;" ::: "memory");
    __syncthreads();
    CONVERT(2, 0);
    __syncthreads();

    asm volatile("cp.async.wait_group 0;" ::: "memory");
    __syncthreads();
    CONVERT(3, 1);
    __syncthreads();

    const int a_row  = (lane & 15);
    const int a_koff = (lane >> 4) << 4;
    const int b_r    = (lane & 7);
    const int b_grp  = lane >> 3;
    const int b_nrow = ((b_grp >> 1) << 3) + b_r;
    const int b_koff = (b_grp & 1) << 4;

    for (int nc = 0; nc < 5; ++nc) {
        if (nc < 4) ISSUE_B(nc + 1, (nc + 1) & 1);
        const uint32_t Bcur = Bs_u + (nc & 1) * 32768;

        float acc[2][4][4];
        #pragma unroll
        for (int mi = 0; mi < 2; mi++)
            #pragma unroll
            for (int nj = 0; nj < 4; nj++)
                #pragma unroll
                for (int q = 0; q < 4; q++) acc[mi][nj][q] = 0.f;

        #pragma unroll
        for (int kt = 0; kt < 16; ++kt) {
            const int chunk = kt >> 2;
            const int kb    = (kt & 3) * 32;

            uint32_t af[2][4];
            #pragma unroll
            for (int mi = 0; mi < 2; mi++) {
                int row = wm * 32 + mi * 16 + a_row;
                uint32_t ad = As_u + chunk * 16384 + SWZ(row * 128 + kb + a_koff);
                asm volatile("ldmatrix.sync.aligned.m8n8.x4.shared.b16 {%0,%1,%2,%3}, [%4];"
                             : "=r"(af[mi][0]), "=r"(af[mi][1]), "=r"(af[mi][2]), "=r"(af[mi][3])
                             : "r"(ad));
            }
            uint32_t bf[2][4];
            #pragma unroll
            for (int njp = 0; njp < 2; njp++) {
                int n = wn * 32 + njp * 16 + b_nrow;
                uint32_t bd = Bcur + chunk * 8192 + SWZ(n * 128 + kb + b_koff);
                asm volatile("ldmatrix.sync.aligned.m8n8.x4.shared.b16 {%0,%1,%2,%3}, [%4];"
                             : "=r"(bf[njp][0]), "=r"(bf[njp][1]), "=r"(bf[njp][2]), "=r"(bf[njp][3])
                             : "r"(bd));
            }
            #pragma unroll
            for (int mi = 0; mi < 2; mi++)
                #pragma unroll
                for (int nj = 0; nj < 4; nj++) {
                    uint32_t b0 = bf[nj >> 1][(nj & 1) * 2 + 0];
                    uint32_t b1 = bf[nj >> 1][(nj & 1) * 2 + 1];
                    asm volatile(
                        "mma.sync.aligned.m16n8k16.row.col.f32.bf16.bf16.f32 "
                        "{%0,%1,%2,%3}, {%4,%5,%6,%7}, {%8,%9}, {%0,%1,%2,%3};"
                        : "+f"(acc[mi][nj][0]), "+f"(acc[mi][nj][1]),
                          "+f"(acc[mi][nj][2]), "+f"(acc[mi][nj][3])
                        : "r"(af[mi][0]), "r"(af[mi][1]), "r"(af[mi][2]), "r"(af[mi][3]),
                          "r"(b0), "r"(b1));
                }
        }

        {
            const int colq = (lane & 3) * 2;
            const int rowq = lane >> 2;
            #pragma unroll
            for (int mi = 0; mi < 2; mi++) {
                int r0 = pix0 + wm * 32 + mi * 16 + rowq;
                #pragma unroll
                for (int nj = 0; nj < 4; nj++) {
                    int col = nc * 64 + wn * 32 + nj * 8 + colq;
                    float bs0 = sbias[col], bs1 = sbias[col + 1];
                    float v00 = acc[mi][nj][0] + bs0, v01 = acc[mi][nj][1] + bs1;
                    float v10 = acc[mi][nj][2] + bs0, v11 = acc[mi][nj][3] + bs1;
                    if (nc == 0) {
                        *(float2*)(g_qk + (size_t)r0 * 64 + col)       = make_float2(v00, v01);
                        *(float2*)(g_qk + (size_t)(r0 + 8) * 64 + col) = make_float2(v10, v11);
                    } else {
                        int vcol2 = (col - 64) >> 1;
                        g_vb[(size_t)r0 * 128 + vcol2]       = pack_bf16(v00, v01);
                        g_vb[(size_t)(r0 + 8) * 128 + vcol2] = pack_bf16(v10, v11);
                    }
                }
            }
        }

        if (nc < 4) {
            asm volatile("cp.async.wait_group 0;" ::: "memory");
            __syncthreads();
        }
    }
}

// ---------------------------------------------------------------------------
// Kernel 2: local 3x3 window attention + residual.
//   v-phase rework: VROW=68 (272B cell stride: 16B-aligned, conflict-free
//   LDS.128), uint4 staging, bf16->f32 via bit ops, x residual prefetched.
// ---------------------------------------------------------------------------
#define PTILE 32
#define KCOLS 34
#define VROW  68     // u32 per (r,col) v cell: 64 data + 4 pad

__global__ __launch_bounds__(256)
void attn_kernel(const float* __restrict__ x,
                 const float* __restrict__ gamma,
                 float* __restrict__ out)
{
    __shared__ __align__(16) uint32_t smem_u[3 * KCOLS * VROW];  // 27744 B
    __shared__ float se[PTILE * 9];

    float* sq = (float*)smem_u;                        // [32][33]
    float* sk = (float*)smem_u + PTILE * 33;           // [3][34][33]

    const int tid   = threadIdx.x;
    const int b     = blockIdx.y;
    const int h     = blockIdx.x >> 1;
    const int wbase = (blockIdx.x & 1) * PTILE;
    const int pixrow = b * HW_ + h * W_;
    const float g0 = gamma[0];

    // Phase 1: load q tile + k halo (fp32 from g_qk)
    for (int idx = tid; idx < PTILE * 32; idx += 256) {
        int p = idx >> 5, c = idx & 31;
        sq[p * 33 + c] = g_qk[(size_t)(pixrow + wbase + p) * 64 + c];
    }
    for (int idx = tid; idx < 3 * KCOLS * 32; idx += 256) {
        int c    = idx & 31;
        int rest = idx >> 5;
        int col  = rest % KCOLS;
        int r    = rest / KCOLS;
        int hh   = h + r - 1;
        int ww   = wbase + col - 1;
        float v = 0.f;
        if (hh >= 0 && hh < H_ && ww >= 0 && ww < W_)
            v = g_qk[(size_t)(b * HW_ + hh * W_ + ww) * 64 + 32 + c];
        sk[(r * KCOLS + col) * 33 + c] = v;
    }
    __syncthreads();

    // Energies (288 tasks)
    for (int task = tid; task < PTILE * 9; task += 256) {
        int p = task / 9, j = task % 9;
        int r = j / 3, dx = j % 3;
        const float* qp = sq + p * 33;
        const float* kp = sk + (r * KCOLS + p + dx) * 33;
        float e = 0.f;
        #pragma unroll
        for (int c = 0; c < 32; c++) e = fmaf(qp[c], kp[c], e);
        se[p * 9 + j] = e;
    }
    __syncthreads();

    // Softmax over 9 (OOB zeros stay in denominator, matching reference)
    if (tid < PTILE) {
        float e[9], m = -1e30f;
        #pragma unroll
        for (int j = 0; j < 9; j++) { e[j] = se[tid * 9 + j]; m = fmaxf(m, e[j]); }
        float s = 0.f;
        #pragma unroll
        for (int j = 0; j < 9; j++) { e[j] = expf(e[j] - m); s += e[j]; }
        float inv = 1.f / s;
        #pragma unroll
        for (int j = 0; j < 9; j++) se[tid * 9 + j] = e[j] * inv;
    }
    __syncthreads();

    // Phase 3: v accumulation, 2 chunks of 128 bf16 channels
    const int p  = tid & 31;
    const int cg = tid >> 5;          // 0..7 -> 16 channels each
    float a[9];
    #pragma unroll
    for (int j = 0; j < 9; j++) a[j] = se[p * 9 + j];

    int basej[9];
    #pragma unroll
    for (int j = 0; j < 9; j++)
        basej[j] = ((j / 3) * KCOLS + p + (j % 3)) * VROW + cg * 8;

    for (int chunk = 0; chunk < 2; ++chunk) {
        __syncthreads();
        // stage v halo chunk: 102 cells x 16 uint4 (coalesced LDG.128/STS.128)
        for (int idx = tid; idx < 3 * KCOLS * 16; idx += 256) {
            int q4   = idx & 15;
            int cell = idx >> 4;
            int col  = cell % KCOLS;
            int r    = cell / KCOLS;
            int hh   = h + r - 1;
            int ww   = wbase + col - 1;
            uint4 v = make_uint4(0u, 0u, 0u, 0u);
            if (hh >= 0 && hh < H_ && ww >= 0 && ww < W_)
                v = *(const uint4*)(g_vb + (size_t)(b * HW_ + hh * W_ + ww) * 128
                                    + chunk * 64 + q4 * 4);
            *(uint4*)(smem_u + cell * VROW + q4 * 4) = v;
        }
        __syncthreads();

        // prefetch residual x (16 independent LDGs -> MLP hides DRAM latency)
        const size_t xbase = ((size_t)(b * C_ + chunk * 128 + cg * 16)) * HW_
                           + h * W_ + wbase + p;
        float xr[16];
        #pragma unroll
        for (int i = 0; i < 16; i++) xr[i] = x[xbase + (size_t)i * HW_];

        float acc[16];
        #pragma unroll
        for (int i = 0; i < 16; i++) acc[i] = 0.f;
        #pragma unroll
        for (int j = 0; j < 9; j++) {
            const uint32_t* svp = smem_u + basej[j];
            uint4 w0 = *(const uint4*)(svp);
            uint4 w1 = *(const uint4*)(svp + 4);
            float aj = a[j];
            uint32_t ws[8] = {w0.x, w0.y, w0.z, w0.w, w1.x, w1.y, w1.z, w1.w};
            #pragma unroll
            for (int u = 0; u < 8; u++) {
                float flo = __uint_as_float(ws[u] << 16);
                float fhi = __uint_as_float(ws[u] & 0xffff0000u);
                acc[2 * u + 0] = fmaf(aj, flo, acc[2 * u + 0]);
                acc[2 * u + 1] = fmaf(aj, fhi, acc[2 * u + 1]);
            }
        }

        // out = gamma*o + x  (coalesced along w)
        #pragma unroll
        for (int i = 0; i < 16; i++)
            out[xbase + (size_t)i * HW_] = fmaf(g0, acc[i], xr[i]);
    }
}

// ---------------------------------------------------------------------------
extern "C" void kernel_launch(void* const* d_in, const int* in_sizes, int n_in,
                              void* d_out, int out_size)
{
    const float* x     = (const float*)d_in[0];
    const float* Wq    = (const float*)d_in[1];
    const float* bq    = (const float*)d_in[2];
    const float* Wk    = (const float*)d_in[3];
    const float* bk    = (const float*)d_in[4];
    const float* Wv    = (const float*)d_in[5];
    const float* bv    = (const float*)d_in[6];
    const float* gamma = (const float*)d_in[7];
    float* out = (float*)d_out;

    cudaFuncSetAttribute(qkv_mma_gemm, cudaFuncAttributeMaxDynamicSharedMemorySize, GEMM_SMEM);

    prep_w<<<40, 256>>>(Wq, Wk, Wv);
    qkv_mma_gemm<<<256, 256, GEMM_SMEM>>>(x, bq, bk, bv);

    dim3 agrid(H_ * 2, B_);
    attn_kernel<<<agrid, 256>>>(x, gamma, out);
}

// round 11
// speedup vs baseline: 1.0980x; 1.0066x over previous
#include <cuda_runtime.h>
#include <cuda_bf16.h>
#include <math.h>
#include <stdint.h>

// Problem constants
#define B_  8
#define C_  256
#define H_  64
#define W_  64
#define HW_ 4096
#define NPIX 32768

// Scratch
__device__ float    g_qk[(size_t)NPIX * 64];      // fp32 q(32)|k(32), pixel-major
__device__ uint32_t g_vb[(size_t)NPIX * 128];     // bf16x2 v (256ch), pixel-major
__device__ uint4    g_wb4[320 * 32];              // bf16 W, [n][256ch], n-order q|k|v
__device__ uint4    g_attn4[(size_t)NPIX * 9 / 4]; // softmaxed weights [pix][9] fp32

#define SWZ(o) ((o) ^ (((o) >> 3) & 0x70))

__device__ __forceinline__ uint32_t pack_bf16(float lo, float hi) {
    uint32_t l = (uint32_t)__bfloat16_as_ushort(__float2bfloat16_rn(lo));
    uint32_t h = (uint32_t)__bfloat16_as_ushort(__float2bfloat16_rn(hi));
    return (h << 16) | l;
}

__device__ __forceinline__ void cp16(uint32_t dst, const void* src) {
    asm volatile("cp.async.cg.shared.global [%0], [%1], 16;" :: "r"(dst), "l"(src) : "memory");
}

// ---------------------------------------------------------------------------
// Kernel 0: W -> bf16 (tiny; L2-resident afterwards). grid 40 x 256.
// ---------------------------------------------------------------------------
__global__ __launch_bounds__(256)
void prep_w(const float* __restrict__ Wq, const float* __restrict__ Wk,
            const float* __restrict__ Wv)
{
    int idx = blockIdx.x * 256 + threadIdx.x;          // 0..10239
    int n = idx >> 5, cg = idx & 31;
    const float* row = (n < 32) ? Wq + n * C_
                     : (n < 64) ? Wk + (n - 32) * C_
                                : Wv + (n - 64) * C_;
    const float* p = row + cg * 8;
    uint4 o;
    o.x = pack_bf16(p[0], p[1]); o.y = pack_bf16(p[2], p[3]);
    o.z = pack_bf16(p[4], p[5]); o.w = pack_bf16(p[6], p[7]);
    g_wb4[idx] = o;
}

// ---------------------------------------------------------------------------
// Kernel 1: fused x-convert + QKV GEMM (bf16 mma.sync). Unchanged (known-good).
// ---------------------------------------------------------------------------
#define XST_ROW 528
#define XST_SZ  (64 * XST_ROW)
#define OFF_B   65536
#define OFF_X   131072
#define GEMM_SMEM (OFF_X + 2 * XST_SZ + 1024)

__global__ __launch_bounds__(256)
void qkv_mma_gemm(const float* __restrict__ x,
                  const float* __restrict__ bq, const float* __restrict__ bk,
                  const float* __restrict__ bv)
{
    extern __shared__ unsigned char dsm[];
    __shared__ float sbias[320];

    const int tid  = threadIdx.x;
    const int lane = tid & 31;
    const int wid  = tid >> 5;
    const int wm   = wid >> 1;
    const int wn   = wid & 1;
    const int pix0 = blockIdx.x * 128;
    const int b    = pix0 >> 12;
    const int hw0  = pix0 & 4095;

    unsigned char* base = (unsigned char*)(((uintptr_t)dsm + 1023) & ~(uintptr_t)1023);
    const uint32_t As_u = (uint32_t)__cvta_generic_to_shared(base);
    const uint32_t Bs_u = As_u + OFF_B;
    const uint32_t Xs_u = As_u + OFF_X;

    for (int i = tid; i < 320; i += 256)
        sbias[i] = (i < 32) ? bq[i] : (i < 64) ? bk[i - 32] : bv[i - 64];

    const float* xb = x + ((size_t)b << 20) + hw0;

    #define ISSUE_X(kc, buf) do {                                             \
        uint32_t dst0 = Xs_u + (buf) * XST_SZ;                                \
        _Pragma("unroll")                                                     \
        for (int it = 0; it < 8; ++it) {                                      \
            int u = it * 256 + tid;                                           \
            int c = u >> 5, s = u & 31;                                       \
            cp16(dst0 + c * XST_ROW + s * 16,                                 \
                 xb + (size_t)((kc) * 64 + c) * HW_ + s * 4);                 \
        }                                                                     \
        asm volatile("cp.async.commit_group;" ::: "memory");                  \
    } while (0)

    #define ISSUE_B(nc, buf) do {                                             \
        const uint4* srcB = g_wb4 + (size_t)(nc) * 64 * 32;                   \
        uint32_t bb = Bs_u + (buf) * 32768;                                   \
        _Pragma("unroll")                                                     \
        for (int it = 0; it < 8; ++it) {                                      \
            int u = it * 256 + tid;                                           \
            int n = u >> 5, g = u & 31;                                       \
            cp16(bb + (g >> 3) * 8192 + SWZ(n * 128 + (g & 7) * 16), srcB + u);\
        }                                                                     \
        asm volatile("cp.async.commit_group;" ::: "memory");                  \
    } while (0)

    #define CONVERT(kc, buf) do {                                             \
        const float* xs = (const float*)(base + OFF_X + (buf) * XST_SZ);      \
        unsigned char* dA = base + (kc) * 16384;                              \
        const int p = tid & 127;                                              \
        const int hf = tid >> 7;                                              \
        _Pragma("unroll")                                                     \
        for (int t = 0; t < 16; ++t) {                                        \
            int c2 = hf * 16 + t;                                             \
            uint32_t w = pack_bf16(xs[(2 * c2) * 132 + p],                    \
                                   xs[(2 * c2 + 1) * 132 + p]);               \
            *(uint32_t*)(dA + SWZ(p * 128 + c2 * 4)) = w;                     \
        }                                                                     \
    } while (0)

    ISSUE_X(0, 0);
    ISSUE_X(1, 1);
    ISSUE_B(0, 0);

    asm volatile("cp.async.wait_group 2;" ::: "memory");
    __syncthreads();
    CONVERT(0, 0);
    __syncthreads();
    ISSUE_X(2, 0);

    asm volatile("cp.async.wait_group 2;" ::: "memory");
    __syncthreads();
    CONVERT(1, 1);
    __syncthreads();
    ISSUE_X(3, 1);

    asm volatile("cp.async.wait_group 1;" ::: "memory");
    __syncthreads();
    CONVERT(2, 0);
    __syncthreads();

    asm volatile("cp.async.wait_group 0;" ::: "memory");
    __syncthreads();
    CONVERT(3, 1);
    __syncthreads();

    const int a_row  = (lane & 15);
    const int a_koff = (lane >> 4) << 4;
    const int b_r    = (lane & 7);
    const int b_grp  = lane >> 3;
    const int b_nrow = ((b_grp >> 1) << 3) + b_r;
    const int b_koff = (b_grp & 1) << 4;

    for (int nc = 0; nc < 5; ++nc) {
        if (nc < 4) ISSUE_B(nc + 1, (nc + 1) & 1);
        const uint32_t Bcur = Bs_u + (nc & 1) * 32768;

        float acc[2][4][4];
        #pragma unroll
        for (int mi = 0; mi < 2; mi++)
            #pragma unroll
            for (int nj = 0; nj < 4; nj++)
                #pragma unroll
                for (int q = 0; q < 4; q++) acc[mi][nj][q] = 0.f;

        #pragma unroll
        for (int kt = 0; kt < 16; ++kt) {
            const int chunk = kt >> 2;
            const int kb    = (kt & 3) * 32;

            uint32_t af[2][4];
            #pragma unroll
            for (int mi = 0; mi < 2; mi++) {
                int row = wm * 32 + mi * 16 + a_row;
                uint32_t ad = As_u + chunk * 16384 + SWZ(row * 128 + kb + a_koff);
                asm volatile("ldmatrix.sync.aligned.m8n8.x4.shared.b16 {%0,%1,%2,%3}, [%4];"
                             : "=r"(af[mi][0]), "=r"(af[mi][1]), "=r"(af[mi][2]), "=r"(af[mi][3])
                             : "r"(ad));
            }
            uint32_t bf[2][4];
            #pragma unroll
            for (int njp = 0; njp < 2; njp++) {
                int n = wn * 32 + njp * 16 + b_nrow;
                uint32_t bd = Bcur + chunk * 8192 + SWZ(n * 128 + kb + b_koff);
                asm volatile("ldmatrix.sync.aligned.m8n8.x4.shared.b16 {%0,%1,%2,%3}, [%4];"
                             : "=r"(bf[njp][0]), "=r"(bf[njp][1]), "=r"(bf[njp][2]), "=r"(bf[njp][3])
                             : "r"(bd));
            }
            #pragma unroll
            for (int mi = 0; mi < 2; mi++)
                #pragma unroll
                for (int nj = 0; nj < 4; nj++) {
                    uint32_t b0 = bf[nj >> 1][(nj & 1) * 2 + 0];
                    uint32_t b1 = bf[nj >> 1][(nj & 1) * 2 + 1];
                    asm volatile(
                        "mma.sync.aligned.m16n8k16.row.col.f32.bf16.bf16.f32 "
                        "{%0,%1,%2,%3}, {%4,%5,%6,%7}, {%8,%9}, {%0,%1,%2,%3};"
                        : "+f"(acc[mi][nj][0]), "+f"(acc[mi][nj][1]),
                          "+f"(acc[mi][nj][2]), "+f"(acc[mi][nj][3])
                        : "r"(af[mi][0]), "r"(af[mi][1]), "r"(af[mi][2]), "r"(af[mi][3]),
                          "r"(b0), "r"(b1));
                }
        }

        {
            const int colq = (lane & 3) * 2;
            const int rowq = lane >> 2;
            #pragma unroll
            for (int mi = 0; mi < 2; mi++) {
                int r0 = pix0 + wm * 32 + mi * 16 + rowq;
                #pragma unroll
                for (int nj = 0; nj < 4; nj++) {
                    int col = nc * 64 + wn * 32 + nj * 8 + colq;
                    float bs0 = sbias[col], bs1 = sbias[col + 1];
                    float v00 = acc[mi][nj][0] + bs0, v01 = acc[mi][nj][1] + bs1;
                    float v10 = acc[mi][nj][2] + bs0, v11 = acc[mi][nj][3] + bs1;
                    if (nc == 0) {
                        *(float2*)(g_qk + (size_t)r0 * 64 + col)       = make_float2(v00, v01);
                        *(float2*)(g_qk + (size_t)(r0 + 8) * 64 + col) = make_float2(v10, v11);
                    } else {
                        int vcol2 = (col - 64) >> 1;
                        g_vb[(size_t)r0 * 128 + vcol2]       = pack_bf16(v00, v01);
                        g_vb[(size_t)(r0 + 8) * 128 + vcol2] = pack_bf16(v10, v11);
                    }
                }
            }
        }

        if (nc < 4) {
            asm volatile("cp.async.wait_group 0;" ::: "memory");
            __syncthreads();
        }
    }
}

// ---------------------------------------------------------------------------
// Kernel 2a: energies + softmax -> g_attn (fp32 weights, [pix][9]).
// ---------------------------------------------------------------------------
#define PTILE 32
#define KCOLS 34

__global__ __launch_bounds__(256)
void attn_energy(const float* __restrict__ dummy)
{
    __shared__ float sq[PTILE * 33];
    __shared__ float sk[3 * KCOLS * 33];
    __shared__ __align__(16) float se[PTILE * 9];

    const int tid   = threadIdx.x;
    const int b     = blockIdx.y;
    const int h     = blockIdx.x >> 1;
    const int wbase = (blockIdx.x & 1) * PTILE;
    const int pixrow = b * HW_ + h * W_;

    for (int idx = tid; idx < PTILE * 32; idx += 256) {
        int p = idx >> 5, c = idx & 31;
        sq[p * 33 + c] = g_qk[(size_t)(pixrow + wbase + p) * 64 + c];
    }
    for (int idx = tid; idx < 3 * KCOLS * 32; idx += 256) {
        int c    = idx & 31;
        int rest = idx >> 5;
        int col  = rest % KCOLS;
        int r    = rest / KCOLS;
        int hh   = h + r - 1;
        int ww   = wbase + col - 1;
        float v = 0.f;
        if (hh >= 0 && hh < H_ && ww >= 0 && ww < W_)
            v = g_qk[(size_t)(b * HW_ + hh * W_ + ww) * 64 + 32 + c];
        sk[(r * KCOLS + col) * 33 + c] = v;
    }
    __syncthreads();

    for (int task = tid; task < PTILE * 9; task += 256) {
        int p = task / 9, j = task % 9;
        int r = j / 3, dx = j % 3;
        const float* qp = sq + p * 33;
        const float* kp = sk + (r * KCOLS + p + dx) * 33;
        float e = 0.f;
        #pragma unroll
        for (int c = 0; c < 32; c++) e = fmaf(qp[c], kp[c], e);
        se[p * 9 + j] = e;
    }
    __syncthreads();

    if (tid < PTILE) {
        float e[9], m = -1e30f;
        #pragma unroll
        for (int j = 0; j < 9; j++) { e[j] = se[tid * 9 + j]; m = fmaxf(m, e[j]); }
        float s = 0.f;
        #pragma unroll
        for (int j = 0; j < 9; j++) { e[j] = expf(e[j] - m); s += e[j]; }
        float inv = 1.f / s;
        #pragma unroll
        for (int j = 0; j < 9; j++) se[tid * 9 + j] = e[j] * inv;
    }
    __syncthreads();

    // write 288 floats = 72 uint4 (aligned: (pixrow+wbase)*9 is mult of 4)
    if (tid < 72) {
        size_t base4 = (size_t)(pixrow + wbase) * 9 / 4;
        g_attn4[base4 + tid] = ((const uint4*)se)[tid];
    }
}

// ---------------------------------------------------------------------------
// Kernel 2b: apply weights to v + residual. Streaming shape:
//   grid (wtile*4chunks=8, h=64, b=8) = 4096 blocks, 256 threads.
//   Each block: one 64-channel chunk for 32 pixels. One barrier.
//   Cell stride 36 u32 (144B): 16B-aligned, conflict-free LDS.128.
// ---------------------------------------------------------------------------
#define VCELL 36

__global__ __launch_bounds__(256)
void attn_apply(const float* __restrict__ x,
                const float* __restrict__ gamma,
                float* __restrict__ out)
{
    __shared__ __align__(16) uint32_t sv[3 * KCOLS * VCELL];   // 14688 B
    __shared__ __align__(16) float sa[PTILE * 9];

    const int tid   = threadIdx.x;
    const int wtile = blockIdx.x & 1;
    const int chunk = blockIdx.x >> 1;          // 0..3 -> channels chunk*64..
    const int h     = blockIdx.y;
    const int b     = blockIdx.z;
    const int wbase = wtile * PTILE;
    const float g0 = gamma[0];

    const int p  = tid & 31;
    const int cg = tid >> 5;                    // 0..7 -> 8 channels each

    // x residual prefetch first (independent LDGs, in flight during staging)
    const size_t xbase = ((size_t)(b * C_ + chunk * 64 + cg * 8)) * HW_
                       + h * W_ + wbase + p;
    float xr[8];
    #pragma unroll
    for (int i = 0; i < 8; i++) xr[i] = x[xbase + (size_t)i * HW_];

    // stage v halo chunk: 102 cells x 8 uint4
    for (int idx = tid; idx < 3 * KCOLS * 8; idx += 256) {
        int q4   = idx & 7;
        int cell = idx >> 3;
        int col  = cell % KCOLS;
        int r    = cell / KCOLS;
        int hh   = h + r - 1;
        int ww   = wbase + col - 1;
        uint4 v = make_uint4(0u, 0u, 0u, 0u);
        if (hh >= 0 && hh < H_ && ww >= 0 && ww < W_)
            v = *(const uint4*)(g_vb + (size_t)(b * HW_ + hh * W_ + ww) * 128
                                + chunk * 32 + q4 * 4);
        *(uint4*)(sv + cell * VCELL + q4 * 4) = v;
    }
    // stage weights: 72 uint4
    if (tid < 72) {
        size_t base4 = (size_t)(b * HW_ + h * W_ + wbase) * 9 / 4;
        ((uint4*)sa)[tid] = g_attn4[base4 + tid];
    }
    __syncthreads();

    float a[9];
    #pragma unroll
    for (int j = 0; j < 9; j++) a[j] = sa[p * 9 + j];

    float acc[8];
    #pragma unroll
    for (int i = 0; i < 8; i++) acc[i] = 0.f;

    #pragma unroll
    for (int j = 0; j < 9; j++) {
        const uint32_t* svp = sv + ((j / 3) * KCOLS + p + (j % 3)) * VCELL + cg * 4;
        uint4 w = *(const uint4*)svp;
        float aj = a[j];
        uint32_t ws[4] = {w.x, w.y, w.z, w.w};
        #pragma unroll
        for (int u = 0; u < 4; u++) {
            float flo = __uint_as_float(ws[u] << 16);
            float fhi = __uint_as_float(ws[u] & 0xffff0000u);
            acc[2 * u + 0] = fmaf(aj, flo, acc[2 * u + 0]);
            acc[2 * u + 1] = fmaf(aj, fhi, acc[2 * u + 1]);
        }
    }

    #pragma unroll
    for (int i = 0; i < 8; i++)
        out[xbase + (size_t)i * HW_] = fmaf(g0, acc[i], xr[i]);
}

// ---------------------------------------------------------------------------
extern "C" void kernel_launch(void* const* d_in, const int* in_sizes, int n_in,
                              void* d_out, int out_size)
{
    const float* x     = (const float*)d_in[0];
    const float* Wq    = (const float*)d_in[1];
    const float* bq    = (const float*)d_in[2];
    const float* Wk    = (const float*)d_in[3];
    const float* bk    = (const float*)d_in[4];
    const float* Wv    = (const float*)d_in[5];
    const float* bv    = (const float*)d_in[6];
    const float* gamma = (const float*)d_in[7];
    float* out = (float*)d_out;

    cudaFuncSetAttribute(qkv_mma_gemm, cudaFuncAttributeMaxDynamicSharedMemorySize, GEMM_SMEM);

    prep_w<<<40, 256>>>(Wq, Wk, Wv);
    qkv_mma_gemm<<<256, 256, GEMM_SMEM>>>(x, bq, bk, bv);

    dim3 egrid(H_ * 2, B_);
    attn_energy<<<egrid, 256>>>(x);

    dim3 agrid(8, H_, B_);
    attn_apply<<<agrid, 256>>>(x, gamma, out);
}

// round 12
// speedup vs baseline: 1.1983x; 1.0914x over previous
#include <cuda_runtime.h>
#include <cuda_bf16.h>
#include <math.h>
#include <stdint.h>

// Problem constants
#define B_  8
#define C_  256
#define H_  64
#define W_  64
#define HW_ 4096
#define NPIX 32768

// Scratch
__device__ float    g_qk[(size_t)NPIX * 64];      // fp32 q(32)|k(32), pixel-major
__device__ uint32_t g_vb[(size_t)NPIX * 128];     // bf16x2 v (256ch), pixel-major
__device__ uint4    g_wb4[320 * 32];              // bf16 W, [n][256ch], n-order q|k|v
__device__ uint4    g_attn4[(size_t)NPIX * 9 / 4]; // softmaxed weights [pix][9] fp32

#define SWZ(o) ((o) ^ (((o) >> 3) & 0x70))

__device__ __forceinline__ uint32_t pack_bf16(float lo, float hi) {
    uint32_t l = (uint32_t)__bfloat16_as_ushort(__float2bfloat16_rn(lo));
    uint32_t h = (uint32_t)__bfloat16_as_ushort(__float2bfloat16_rn(hi));
    return (h << 16) | l;
}

__device__ __forceinline__ void cp16(uint32_t dst, const void* src) {
    asm volatile("cp.async.cg.shared.global [%0], [%1], 16;" :: "r"(dst), "l"(src) : "memory");
}

// ---------------------------------------------------------------------------
// Kernel 0: W -> bf16 (tiny; L2-resident afterwards). grid 40 x 256.
// ---------------------------------------------------------------------------
__global__ __launch_bounds__(256)
void prep_w(const float* __restrict__ Wq, const float* __restrict__ Wk,
            const float* __restrict__ Wv)
{
    int idx = blockIdx.x * 256 + threadIdx.x;          // 0..10239
    int n = idx >> 5, cg = idx & 31;
    const float* row = (n < 32) ? Wq + n * C_
                     : (n < 64) ? Wk + (n - 32) * C_
                                : Wv + (n - 64) * C_;
    const float* p = row + cg * 8;
    uint4 o;
    o.x = pack_bf16(p[0], p[1]); o.y = pack_bf16(p[2], p[3]);
    o.z = pack_bf16(p[4], p[5]); o.w = pack_bf16(p[6], p[7]);
    g_wb4[idx] = o;
}

// ---------------------------------------------------------------------------
// Kernel 1: fused x-convert + QKV GEMM (bf16 mma.sync). Unchanged (known-good).
// ---------------------------------------------------------------------------
#define XST_ROW 528
#define XST_SZ  (64 * XST_ROW)
#define OFF_B   65536
#define OFF_X   131072
#define GEMM_SMEM (OFF_X + 2 * XST_SZ + 1024)

__global__ __launch_bounds__(256)
void qkv_mma_gemm(const float* __restrict__ x,
                  const float* __restrict__ bq, const float* __restrict__ bk,
                  const float* __restrict__ bv)
{
    extern __shared__ unsigned char dsm[];
    __shared__ float sbias[320];

    const int tid  = threadIdx.x;
    const int lane = tid & 31;
    const int wid  = tid >> 5;
    const int wm   = wid >> 1;
    const int wn   = wid & 1;
    const int pix0 = blockIdx.x * 128;
    const int b    = pix0 >> 12;
    const int hw0  = pix0 & 4095;

    unsigned char* base = (unsigned char*)(((uintptr_t)dsm + 1023) & ~(uintptr_t)1023);
    const uint32_t As_u = (uint32_t)__cvta_generic_to_shared(base);
    const uint32_t Bs_u = As_u + OFF_B;
    const uint32_t Xs_u = As_u + OFF_X;

    for (int i = tid; i < 320; i += 256)
        sbias[i] = (i < 32) ? bq[i] : (i < 64) ? bk[i - 32] : bv[i - 64];

    const float* xb = x + ((size_t)b << 20) + hw0;

    #define ISSUE_X(kc, buf) do {                                             \
        uint32_t dst0 = Xs_u + (buf) * XST_SZ;                                \
        _Pragma("unroll")                                                     \
        for (int it = 0; it < 8; ++it) {                                      \
            int u = it * 256 + tid;                                           \
            int c = u >> 5, s = u & 31;                                       \
            cp16(dst0 + c * XST_ROW + s * 16,                                 \
                 xb + (size_t)((kc) * 64 + c) * HW_ + s * 4);                 \
        }                                                                     \
        asm volatile("cp.async.commit_group;" ::: "memory");                  \
    } while (0)

    #define ISSUE_B(nc, buf) do {                                             \
        const uint4* srcB = g_wb4 + (size_t)(nc) * 64 * 32;                   \
        uint32_t bb = Bs_u + (buf) * 32768;                                   \
        _Pragma("unroll")                                                     \
        for (int it = 0; it < 8; ++it) {                                      \
            int u = it * 256 + tid;                                           \
            int n = u >> 5, g = u & 31;                                       \
            cp16(bb + (g >> 3) * 8192 + SWZ(n * 128 + (g & 7) * 16), srcB + u);\
        }                                                                     \
        asm volatile("cp.async.commit_group;" ::: "memory");                  \
    } while (0)

    #define CONVERT(kc, buf) do {                                             \
        const float* xs = (const float*)(base + OFF_X + (buf) * XST_SZ);      \
        unsigned char* dA = base + (kc) * 16384;                              \
        const int p = tid & 127;                                              \
        const int hf = tid >> 7;                                              \
        _Pragma("unroll")                                                     \
        for (int t = 0; t < 16; ++t) {                                        \
            int c2 = hf * 16 + t;                                             \
            uint32_t w = pack_bf16(xs[(2 * c2) * 132 + p],                    \
                                   xs[(2 * c2 + 1) * 132 + p]);               \
            *(uint32_t*)(dA + SWZ(p * 128 + c2 * 4)) = w;                     \
        }                                                                     \
    } while (0)

    ISSUE_X(0, 0);
    ISSUE_X(1, 1);
    ISSUE_B(0, 0);

    asm volatile("cp.async.wait_group 2;" ::: "memory");
    __syncthreads();
    CONVERT(0, 0);
    __syncthreads();
    ISSUE_X(2, 0);

    asm volatile("cp.async.wait_group 2;" ::: "memory");
    __syncthreads();
    CONVERT(1, 1);
    __syncthreads();
    ISSUE_X(3, 1);

    asm volatile("cp.async.wait_group 1;" ::: "memory");
    __syncthreads();
    CONVERT(2, 0);
    __syncthreads();

    asm volatile("cp.async.wait_group 0;" ::: "memory");
    __syncthreads();
    CONVERT(3, 1);
    __syncthreads();

    const int a_row  = (lane & 15);
    const int a_koff = (lane >> 4) << 4;
    const int b_r    = (lane & 7);
    const int b_grp  = lane >> 3;
    const int b_nrow = ((b_grp >> 1) << 3) + b_r;
    const int b_koff = (b_grp & 1) << 4;

    for (int nc = 0; nc < 5; ++nc) {
        if (nc < 4) ISSUE_B(nc + 1, (nc + 1) & 1);
        const uint32_t Bcur = Bs_u + (nc & 1) * 32768;

        float acc[2][4][4];
        #pragma unroll
        for (int mi = 0; mi < 2; mi++)
            #pragma unroll
            for (int nj = 0; nj < 4; nj++)
                #pragma unroll
                for (int q = 0; q < 4; q++) acc[mi][nj][q] = 0.f;

        #pragma unroll
        for (int kt = 0; kt < 16; ++kt) {
            const int chunk = kt >> 2;
            const int kb    = (kt & 3) * 32;

            uint32_t af[2][4];
            #pragma unroll
            for (int mi = 0; mi < 2; mi++) {
                int row = wm * 32 + mi * 16 + a_row;
                uint32_t ad = As_u + chunk * 16384 + SWZ(row * 128 + kb + a_koff);
                asm volatile("ldmatrix.sync.aligned.m8n8.x4.shared.b16 {%0,%1,%2,%3}, [%4];"
                             : "=r"(af[mi][0]), "=r"(af[mi][1]), "=r"(af[mi][2]), "=r"(af[mi][3])
                             : "r"(ad));
            }
            uint32_t bf[2][4];
            #pragma unroll
            for (int njp = 0; njp < 2; njp++) {
                int n = wn * 32 + njp * 16 + b_nrow;
                uint32_t bd = Bcur + chunk * 8192 + SWZ(n * 128 + kb + b_koff);
                asm volatile("ldmatrix.sync.aligned.m8n8.x4.shared.b16 {%0,%1,%2,%3}, [%4];"
                             : "=r"(bf[njp][0]), "=r"(bf[njp][1]), "=r"(bf[njp][2]), "=r"(bf[njp][3])
                             : "r"(bd));
            }
            #pragma unroll
            for (int mi = 0; mi < 2; mi++)
                #pragma unroll
                for (int nj = 0; nj < 4; nj++) {
                    uint32_t b0 = bf[nj >> 1][(nj & 1) * 2 + 0];
                    uint32_t b1 = bf[nj >> 1][(nj & 1) * 2 + 1];
                    asm volatile(
                        "mma.sync.aligned.m16n8k16.row.col.f32.bf16.bf16.f32 "
                        "{%0,%1,%2,%3}, {%4,%5,%6,%7}, {%8,%9}, {%0,%1,%2,%3};"
                        : "+f"(acc[mi][nj][0]), "+f"(acc[mi][nj][1]),
                          "+f"(acc[mi][nj][2]), "+f"(acc[mi][nj][3])
                        : "r"(af[mi][0]), "r"(af[mi][1]), "r"(af[mi][2]), "r"(af[mi][3]),
                          "r"(b0), "r"(b1));
                }
        }

        {
            const int colq = (lane & 3) * 2;
            const int rowq = lane >> 2;
            #pragma unroll
            for (int mi = 0; mi < 2; mi++) {
                int r0 = pix0 + wm * 32 + mi * 16 + rowq;
                #pragma unroll
                for (int nj = 0; nj < 4; nj++) {
                    int col = nc * 64 + wn * 32 + nj * 8 + colq;
                    float bs0 = sbias[col], bs1 = sbias[col + 1];
                    float v00 = acc[mi][nj][0] + bs0, v01 = acc[mi][nj][1] + bs1;
                    float v10 = acc[mi][nj][2] + bs0, v11 = acc[mi][nj][3] + bs1;
                    if (nc == 0) {
                        *(float2*)(g_qk + (size_t)r0 * 64 + col)       = make_float2(v00, v01);
                        *(float2*)(g_qk + (size_t)(r0 + 8) * 64 + col) = make_float2(v10, v11);
                    } else {
                        int vcol2 = (col - 64) >> 1;
                        g_vb[(size_t)r0 * 128 + vcol2]       = pack_bf16(v00, v01);
                        g_vb[(size_t)(r0 + 8) * 128 + vcol2] = pack_bf16(v10, v11);
                    }
                }
            }
        }

        if (nc < 4) {
            asm volatile("cp.async.wait_group 0;" ::: "memory");
            __syncthreads();
        }
    }
}

// ---------------------------------------------------------------------------
// Kernel 2a: energies + softmax -> g_attn. Row-wide blocks (64 px), uint4
//   staging (g_qk rows are 256B-aligned). grid (H, B) = 512 blocks.
// ---------------------------------------------------------------------------
#define PTILE 32
#define KCOLS 34
#define KC2   66            // 64 + 2 halo
#define EQROW 36            // floats per staged row (32 data + 4 pad)

__global__ __launch_bounds__(256)
void attn_energy(const float* __restrict__ dummy)
{
    __shared__ __align__(16) float sq[64 * EQROW];        //  9216 B
    __shared__ __align__(16) float sk[3 * KC2 * EQROW];   // 28512 B
    __shared__ __align__(16) float se[64 * 9];            //  2304 B

    const int tid    = threadIdx.x;
    const int h      = blockIdx.x;
    const int b      = blockIdx.y;
    const int pixrow = b * HW_ + h * W_;

    // q: 64 px x 8 uint4
    #pragma unroll
    for (int it = 0; it < 2; ++it) {
        int idx = it * 256 + tid;
        int p = idx >> 3, g = idx & 7;
        uint4 v = *(const uint4*)(g_qk + (size_t)(pixrow + p) * 64 + g * 4);
        *(uint4*)(sq + p * EQROW + g * 4) = v;
    }
    // k halo: 3*66 cells x 8 uint4 (zero-padded)
    for (int idx = tid; idx < 3 * KC2 * 8; idx += 256) {
        int g    = idx & 7;
        int cell = idx >> 3;
        int col  = cell % KC2;
        int r    = cell / KC2;
        int hh   = h + r - 1;
        int ww   = col - 1;
        uint4 v = make_uint4(0u, 0u, 0u, 0u);
        if (hh >= 0 && hh < H_ && ww >= 0 && ww < W_)
            v = *(const uint4*)(g_qk + (size_t)(b * HW_ + hh * W_ + ww) * 64 + 32 + g * 4);
        *(uint4*)(sk + cell * EQROW + g * 4) = v;
    }
    __syncthreads();

    // energies: 576 tasks (64 px x 9 slots)
    for (int task = tid; task < 64 * 9; task += 256) {
        int p = task / 9, j = task % 9;
        int r = j / 3, dx = j % 3;
        const float* qp = sq + p * EQROW;
        const float* kp = sk + (r * KC2 + p + dx) * EQROW;
        float e = 0.f;
        #pragma unroll
        for (int c = 0; c < 32; c++) e = fmaf(qp[c], kp[c], e);
        se[p * 9 + j] = e;
    }
    __syncthreads();

    // softmax over 9 (OOB zeros stay in denominator, matching reference)
    if (tid < 64) {
        float e[9], m = -1e30f;
        #pragma unroll
        for (int j = 0; j < 9; j++) { e[j] = se[tid * 9 + j]; m = fmaxf(m, e[j]); }
        float s = 0.f;
        #pragma unroll
        for (int j = 0; j < 9; j++) { e[j] = expf(e[j] - m); s += e[j]; }
        float inv = 1.f / s;
        #pragma unroll
        for (int j = 0; j < 9; j++) se[tid * 9 + j] = e[j] * inv;
    }
    __syncthreads();

    // write 576 floats = 144 uint4 (pixrow*9 is a multiple of 4)
    if (tid < 144) {
        size_t base4 = (size_t)pixrow * 9 / 4;
        g_attn4[base4 + tid] = ((const uint4*)se)[tid];
    }
}

// ---------------------------------------------------------------------------
// Kernel 2b: apply weights to v + residual (unchanged, known-good 22.7us).
// ---------------------------------------------------------------------------
#define VCELL 36

__global__ __launch_bounds__(256)
void attn_apply(const float* __restrict__ x,
                const float* __restrict__ gamma,
                float* __restrict__ out)
{
    __shared__ __align__(16) uint32_t sv[3 * KCOLS * VCELL];   // 14688 B
    __shared__ __align__(16) float sa[PTILE * 9];

    const int tid   = threadIdx.x;
    const int wtile = blockIdx.x & 1;
    const int chunk = blockIdx.x >> 1;          // 0..3 -> channels chunk*64..
    const int h     = blockIdx.y;
    const int b     = blockIdx.z;
    const int wbase = wtile * PTILE;
    const float g0 = gamma[0];

    const int p  = tid & 31;
    const int cg = tid >> 5;                    // 0..7 -> 8 channels each

    // x residual prefetch first (independent LDGs, in flight during staging)
    const size_t xbase = ((size_t)(b * C_ + chunk * 64 + cg * 8)) * HW_
                       + h * W_ + wbase + p;
    float xr[8];
    #pragma unroll
    for (int i = 0; i < 8; i++) xr[i] = x[xbase + (size_t)i * HW_];

    // stage v halo chunk: 102 cells x 8 uint4
    for (int idx = tid; idx < 3 * KCOLS * 8; idx += 256) {
        int q4   = idx & 7;
        int cell = idx >> 3;
        int col  = cell % KCOLS;
        int r    = cell / KCOLS;
        int hh   = h + r - 1;
        int ww   = wbase + col - 1;
        uint4 v = make_uint4(0u, 0u, 0u, 0u);
        if (hh >= 0 && hh < H_ && ww >= 0 && ww < W_)
            v = *(const uint4*)(g_vb + (size_t)(b * HW_ + hh * W_ + ww) * 128
                                + chunk * 32 + q4 * 4);
        *(uint4*)(sv + cell * VCELL + q4 * 4) = v;
    }
    // stage weights: 72 uint4
    if (tid < 72) {
        size_t base4 = (size_t)(b * HW_ + h * W_ + wbase) * 9 / 4;
        ((uint4*)sa)[tid] = g_attn4[base4 + tid];
    }
    __syncthreads();

    float a[9];
    #pragma unroll
    for (int j = 0; j < 9; j++) a[j] = sa[p * 9 + j];

    float acc[8];
    #pragma unroll
    for (int i = 0; i < 8; i++) acc[i] = 0.f;

    #pragma unroll
    for (int j = 0; j < 9; j++) {
        const uint32_t* svp = sv + ((j / 3) * KCOLS + p + (j % 3)) * VCELL + cg * 4;
        uint4 w = *(const uint4*)svp;
        float aj = a[j];
        uint32_t ws[4] = {w.x, w.y, w.z, w.w};
        #pragma unroll
        for (int u = 0; u < 4; u++) {
            float flo = __uint_as_float(ws[u] << 16);
            float fhi = __uint_as_float(ws[u] & 0xffff0000u);
            acc[2 * u + 0] = fmaf(aj, flo, acc[2 * u + 0]);
            acc[2 * u + 1] = fmaf(aj, fhi, acc[2 * u + 1]);
        }
    }

    #pragma unroll
    for (int i = 0; i < 8; i++)
        out[xbase + (size_t)i * HW_] = fmaf(g0, acc[i], xr[i]);
}

// ---------------------------------------------------------------------------
extern "C" void kernel_launch(void* const* d_in, const int* in_sizes, int n_in,
                              void* d_out, int out_size)
{
    const float* x     = (const float*)d_in[0];
    const float* Wq    = (const float*)d_in[1];
    const float* bq    = (const float*)d_in[2];
    const float* Wk    = (const float*)d_in[3];
    const float* bk    = (const float*)d_in[4];
    const float* Wv    = (const float*)d_in[5];
    const float* bv    = (const float*)d_in[6];
    const float* gamma = (const float*)d_in[7];
    float* out = (float*)d_out;

    cudaFuncSetAttribute(qkv_mma_gemm, cudaFuncAttributeMaxDynamicSharedMemorySize, GEMM_SMEM);

    prep_w<<<40, 256>>>(Wq, Wk, Wv);
    qkv_mma_gemm<<<256, 256, GEMM_SMEM>>>(x, bq, bk, bv);

    dim3 egrid(H_, B_);
    attn_energy<<<egrid, 256>>>(x);

    dim3 agrid(8, H_, B_);
    attn_apply<<<agrid, 256>>>(x, gamma, out);
}